// round 15
// baseline (speedup 1.0000x reference)
#include <cuda_runtime.h>
#include <cstdint>

// H100SmartEmbedding: out[r, :] = concat(price[0], size[0], exch[r%3], pair[r%7],
//                                        level[r%15], time[r%31]), 6 x 128 fp32.
//
// Period trick: lcm(3,7,15,31) = 3255. Work in ROW PAIRS: pairs p ≡ residue
// (mod 3255) -> rows 2p,2p+1 have block-constant residues mod 3/7/15/31, so
// each thread loads its 32B table chunk ONCE; mainloop is a pure store stream.
//
// R15 probe (last untried store-policy cell): st.global.wt (write-through)
// instead of .cs — removes the L2 dirty-line/writeback lifecycle from the
// store path entirely. Paired with SPLITP=12 (best observed kernel duration).
// Model predicts neutral (~58us); any move either way completes the matrix.

#define PERIOD 3255
#define SPLITP 12   // splits per residue class (over pairs) -> grid 39060

__global__ void __launch_bounds__(192)
smart_embedding_kernel(const float4* __restrict__ price,
                       const float4* __restrict__ size_,
                       const float4* __restrict__ exch,
                       const float4* __restrict__ pair,
                       const float4* __restrict__ level,
                       const float4* __restrict__ timew,
                       float* __restrict__ out,
                       int num_features)
{
    const int t   = threadIdx.x;     // 0..191
    const int rip = t / 96;          // row-in-pair: 0 or 1
    const int u   = t % 96;          // chunk within row (96 x 8 floats = 768)
    const int sec = u >> 4;          // section 0..5
    const int c8  = u & 15;          // 32B chunk within the 128-float section

    const int residue = blockIdx.x;  // pair residue, 0..PERIOD-1
    const int chunk   = blockIdx.y;  // 0..SPLITP-1

    // Row this lane serves at pair p: r = 2p + rip, p ≡ residue (mod 3255)
    // -> r ≡ 2*residue + rip (mod 3255): table rows are block-constant.
    const int rbase = 2 * residue + rip;

    // One-time 32B table load per thread (tables: 31.75KB total, L1/L2-hot).
    const float4* src;
    if (sec == 0) {
        src = price + c8 * 2;
    } else if (sec == 1) {
        src = size_ + c8 * 2;
    } else if (sec == 2) {
        src = exch + (rbase % 3) * 32 + c8 * 2;
    } else if (sec == 3) {
        src = pair + (rbase % 7) * 32 + c8 * 2;
    } else if (sec == 4) {
        src = level + (rbase % 15) * 32 + c8 * 2;
    } else {
        src = timew + (rbase % 31) * 32 + c8 * 2;
    }
    const float4 v0 = __ldg(src);
    const float4 v1 = __ldg(src + 1);

    // Pairs handled by this block: residue + chunk*PERIOD, step SPLITP*PERIOD.
    const int num_pairs = num_features >> 1;
    int p = residue + chunk * PERIOD;
    if (p >= num_pairs) return;

    const int    pstride = SPLITP * PERIOD;
    const size_t stepf   = (size_t)pstride * 1536;   // floats per pair-stride
    float* ptr = out + (size_t)p * 1536 + t * 8;

    // Pure 256-bit WRITE-THROUGH store stream (no L2 dirty-line lifecycle).
    #pragma unroll 4
    for (; p < num_pairs; p += pstride) {
        asm volatile(
            "st.global.wt.v8.f32 [%0], {%1, %2, %3, %4, %5, %6, %7, %8};"
            :: "l"(ptr),
               "f"(v0.x), "f"(v0.y), "f"(v0.z), "f"(v0.w),
               "f"(v1.x), "f"(v1.y), "f"(v1.z), "f"(v1.w)
            : "memory");
        ptr += stepf;
    }
}

// Tail for odd num_features (not hit for this dataset: 131072 is even).
__global__ void __launch_bounds__(192)
smart_embedding_tail(const float4* __restrict__ price,
                     const float4* __restrict__ size_,
                     const float4* __restrict__ exch,
                     const float4* __restrict__ pair,
                     const float4* __restrict__ level,
                     const float4* __restrict__ timew,
                     float4* __restrict__ out,
                     int row)
{
    const int t   = threadIdx.x;
    const int sec = t >> 5;
    const int c4  = t & 31;
    float4 v;
    if (sec == 0)      v = __ldg(&price[c4]);
    else if (sec == 1) v = __ldg(&size_[c4]);
    else if (sec == 2) v = __ldg(&exch[(row % 3) * 32 + c4]);
    else if (sec == 3) v = __ldg(&pair[(row % 7) * 32 + c4]);
    else if (sec == 4) v = __ldg(&level[(row % 15) * 32 + c4]);
    else               v = __ldg(&timew[(row % 31) * 32 + c4]);
    out[(size_t)row * 192 + t] = v;
}

extern "C" void kernel_launch(void* const* d_in, const int* in_sizes, int n_in,
                              void* d_out, int out_size)
{
    const float4* price = (const float4*)d_in[0];
    const float4* size_ = (const float4*)d_in[1];
    const float4* exch  = (const float4*)d_in[2];
    const float4* pair  = (const float4*)d_in[3];
    const float4* level = (const float4*)d_in[4];
    const float4* timew = (const float4*)d_in[5];

    // num_features lives in device memory (d_in[6]); deriving it host-side
    // from out_size keeps kernel_launch graph-capturable.
    const int num_features = out_size / 768;

    dim3 grid(PERIOD, SPLITP, 1);
    smart_embedding_kernel<<<grid, 192>>>(price, size_, exch, pair, level,
                                          timew, (float*)d_out, num_features);
    if (num_features & 1) {
        smart_embedding_tail<<<1, 192>>>(price, size_, exch, pair, level,
                                         timew, (float4*)d_out,
                                         num_features - 1);
    }
}

// round 16
// speedup vs baseline: 1.0006x; 1.0006x over previous
#include <cuda_runtime.h>
#include <cstdint>

// H100SmartEmbedding: out[r, :] = concat(price[0], size[0], exch[r%3], pair[r%7],
//                                        level[r%15], time[r%31]), 6 x 128 fp32.
//
// FINAL KERNEL (R8; best of 15 rounds: 57.82us, reproduced x4).
//
// Structure: lcm(3,7,15,31) = 3255. Work in ROW PAIRS: pairs p ≡ residue
// (mod 3255) -> rows 2p,2p+1 have block-constant residues mod 3/7/15/31, so
// each thread loads its 32B table chunk ONCE; the mainloop is a pure
// 256-bit store stream (st.global.cs.v8.f32), SPLITP=6 -> grid 19530.
//
// Roofline verdict (measured across 15 rounds): pinned at the HBM3e
// pure-write ceiling, ~6.0 TB/s = ~75% of the 8 TB/s mixed-traffic spec.
//   - Front-ends equal: STG.128 = STG.256 = TMA bulk-async.
//   - Store policies equal: write-back = .cs evict-first = .wt write-through.
//   - Split bracket {3: 59.4, 6: 57.8, 12: 57.8} -> flat optimum at 6-12.
//   - Block shape, unroll depth, grid layout: all neutral.
//   - SM-side pipes <31% of any resource throughout.

#define PERIOD 3255
#define SPLITP 6   // splits per residue class (over pairs) -> grid 19530

__global__ void __launch_bounds__(192)
smart_embedding_kernel(const float4* __restrict__ price,
                       const float4* __restrict__ size_,
                       const float4* __restrict__ exch,
                       const float4* __restrict__ pair,
                       const float4* __restrict__ level,
                       const float4* __restrict__ timew,
                       float* __restrict__ out,
                       int num_features)
{
    const int t   = threadIdx.x;     // 0..191
    const int rip = t / 96;          // row-in-pair: 0 or 1
    const int u   = t % 96;          // chunk within row (96 x 8 floats = 768)
    const int sec = u >> 4;          // section 0..5
    const int c8  = u & 15;          // 32B chunk within the 128-float section

    const int residue = blockIdx.x;  // pair residue, 0..PERIOD-1
    const int chunk   = blockIdx.y;  // 0..SPLITP-1

    // Row this lane serves at pair p: r = 2p + rip, p ≡ residue (mod 3255)
    // -> r ≡ 2*residue + rip (mod 3255): table rows are block-constant.
    const int rbase = 2 * residue + rip;

    // One-time 32B table load per thread (tables: 31.75KB total, L1/L2-hot).
    const float4* src;
    if (sec == 0) {
        src = price + c8 * 2;
    } else if (sec == 1) {
        src = size_ + c8 * 2;
    } else if (sec == 2) {
        src = exch + (rbase % 3) * 32 + c8 * 2;
    } else if (sec == 3) {
        src = pair + (rbase % 7) * 32 + c8 * 2;
    } else if (sec == 4) {
        src = level + (rbase % 15) * 32 + c8 * 2;
    } else {
        src = timew + (rbase % 31) * 32 + c8 * 2;
    }
    const float4 v0 = __ldg(src);
    const float4 v1 = __ldg(src + 1);

    // Pairs handled by this block: residue + chunk*PERIOD, step SPLITP*PERIOD.
    const int num_pairs = num_features >> 1;
    int p = residue + chunk * PERIOD;
    if (p >= num_pairs) return;

    const int    pstride = SPLITP * PERIOD;
    const size_t stepf   = (size_t)pstride * 1536;   // floats per pair-stride
    float* ptr = out + (size_t)p * 1536 + t * 8;

    // Pure 256-bit store stream; .cs = evict-first for write-once data.
    #pragma unroll 4
    for (; p < num_pairs; p += pstride) {
        asm volatile(
            "st.global.cs.v8.f32 [%0], {%1, %2, %3, %4, %5, %6, %7, %8};"
            :: "l"(ptr),
               "f"(v0.x), "f"(v0.y), "f"(v0.z), "f"(v0.w),
               "f"(v1.x), "f"(v1.y), "f"(v1.z), "f"(v1.w)
            : "memory");
        ptr += stepf;
    }
}

// Tail for odd num_features (not hit for this dataset: 131072 is even).
__global__ void __launch_bounds__(192)
smart_embedding_tail(const float4* __restrict__ price,
                     const float4* __restrict__ size_,
                     const float4* __restrict__ exch,
                     const float4* __restrict__ pair,
                     const float4* __restrict__ level,
                     const float4* __restrict__ timew,
                     float4* __restrict__ out,
                     int row)
{
    const int t   = threadIdx.x;
    const int sec = t >> 5;
    const int c4  = t & 31;
    float4 v;
    if (sec == 0)      v = __ldg(&price[c4]);
    else if (sec == 1) v = __ldg(&size_[c4]);
    else if (sec == 2) v = __ldg(&exch[(row % 3) * 32 + c4]);
    else if (sec == 3) v = __ldg(&pair[(row % 7) * 32 + c4]);
    else if (sec == 4) v = __ldg(&level[(row % 15) * 32 + c4]);
    else               v = __ldg(&timew[(row % 31) * 32 + c4]);
    out[(size_t)row * 192 + t] = v;
}

extern "C" void kernel_launch(void* const* d_in, const int* in_sizes, int n_in,
                              void* d_out, int out_size)
{
    const float4* price = (const float4*)d_in[0];
    const float4* size_ = (const float4*)d_in[1];
    const float4* exch  = (const float4*)d_in[2];
    const float4* pair  = (const float4*)d_in[3];
    const float4* level = (const float4*)d_in[4];
    const float4* timew = (const float4*)d_in[5];

    // num_features lives in device memory (d_in[6]); deriving it host-side
    // from out_size keeps kernel_launch graph-capturable.
    const int num_features = out_size / 768;

    dim3 grid(PERIOD, SPLITP, 1);
    smart_embedding_kernel<<<grid, 192>>>(price, size_, exch, pair, level,
                                          timew, (float*)d_out, num_features);
    if (num_features & 1) {
        smart_embedding_tail<<<1, 192>>>(price, size_, exch, pair, level,
                                         timew, (float4*)d_out,
                                         num_features - 1);
    }
}